// round 16
// baseline (speedup 1.0000x reference)
#include <cuda_runtime.h>
#include <cuda_fp16.h>
#include <math.h>

#define NN 50000
#define EE 1600000
#define ET (EE + NN)
#define GG 100
#define IN_CH 16
#define H1 4
#define C1 32
#define D1 (H1*C1)
#define C2 32
#define NEG 0.2f

#define DEG_BLOCKS ((EE / 4 + 255) / 256)
#define SCAT_BLOCKS ((EE / 4 + 255) / 256)
#define GEMM1_BLOCKS ((NN + 255) / 256)   // 1024-thread blocks: 256 nodes each

// ---------------- scratch ----------------
__device__ __align__(16) int g_deg[NN + 4];
__device__ __align__(16) int g_rowptr[NN + 4];
__device__ __align__(16) int g_cursor[NN + 4];
__device__ __align__(16) int g_csrsrc[ET + 4];
__device__ __align__(16) __half g_h1h[NN * D1];
__device__ __align__(16) float  g_as1[NN * H1];
__device__ __align__(16) float  g_ad1[NN * H1];
__device__ __align__(16) __half g_out1h[NN * D1];
__device__ __align__(16) __half g_h2h[NN * C2];
__device__ float g_as2[NN];
__device__ float g_ad2[NN];
__device__ float g_pool[GG * C2];
__device__ float g_cnt[GG];

// ---------------- degree (int4, 4 edges/thread) + pool init ----------------
__global__ void k_degree(const int* __restrict__ ei) {
    int b = blockIdx.x;
    if (b < DEG_BLOCKS) {
        int e4 = b * 256 + threadIdx.x;
        if (e4 * 4 < EE) {
            int4 d = *(const int4*)(ei + EE + e4 * 4);
            atomicAdd(&g_deg[d.x], 1);
            atomicAdd(&g_deg[d.y], 1);
            atomicAdd(&g_deg[d.z], 1);
            atomicAdd(&g_deg[d.w], 1);
        }
    } else {
        int i = threadIdx.x;
        for (; i < GG * C2; i += 256) g_pool[i] = 0.f;
        int j = threadIdx.x;
        if (j < GG) g_cnt[j] = 0.f;
    }
}

// ---------------- GEMM1 body (flexible block size) ----------------
__device__ __forceinline__ void gemm1_body(int blk,
                        const float* __restrict__ x,
                        const float* __restrict__ W1,
                        const float* __restrict__ as_w,
                        const float* __restrict__ ad_w,
                        float* sW, float* sAs, float* sAd) {
    int t = threadIdx.x;
    int nthr = blockDim.x;
    for (int i = t; i < IN_CH * D1; i += nthr) sW[i] = W1[i];
    if (t < H1 * C1) { sAs[t] = as_w[t]; sAd[t] = ad_w[t]; }
    __syncthreads();

    int warp = t >> 5, lane = t & 31;
    int h = warp & 3;
    int nodes_per_blk = (nthr >> 2);
    int n = blk * nodes_per_blk + (warp >> 2) * 32 + lane;
    if (n >= NN) return;

    float xv[16];
    const float4* xp = (const float4*)(x + (size_t)n * IN_CH);
    #pragma unroll
    for (int i = 0; i < 4; i++) {
        float4 r = xp[i];
        xv[4*i]=r.x; xv[4*i+1]=r.y; xv[4*i+2]=r.z; xv[4*i+3]=r.w;
    }
    float acc[C1];
    #pragma unroll
    for (int c = 0; c < C1; c++) acc[c] = 0.f;
    #pragma unroll
    for (int k = 0; k < IN_CH; k++) {
        float xk = xv[k];
        const float* wrow = sW + k * D1 + h * C1;
        #pragma unroll
        for (int c = 0; c < C1; c++) acc[c] += xk * wrow[c];
    }
    float asum = 0.f, dsum = 0.f;
    #pragma unroll
    for (int c = 0; c < C1; c++) { asum += acc[c] * sAs[h*C1+c]; dsum += acc[c] * sAd[h*C1+c]; }
    g_as1[n * H1 + h] = asum;
    g_ad1[n * H1 + h] = dsum;
    uint4 pk[4];
    unsigned* pu = (unsigned*)pk;
    #pragma unroll
    for (int i = 0; i < 16; i++) {
        __half2 hh = __floats2half2_rn(acc[2*i], acc[2*i+1]);
        pu[i] = *(unsigned*)&hh;
    }
    uint4* hp = (uint4*)(g_h1h + (size_t)n * D1 + h * C1);
    #pragma unroll
    for (int i = 0; i < 4; i++) hp[i] = pk[i];
}

// ---------------- fat kernel: scan + self-loop seed (block 0) + gemm1 (blocks 1..) ----------------
__global__ void __launch_bounds__(1024) k_scan_gemm1(
        const float* __restrict__ x,
        const float* __restrict__ W1,
        const float* __restrict__ as_w,
        const float* __restrict__ ad_w) {
    __shared__ float sW[IN_CH * D1 + 2 * H1 * C1];
    if (blockIdx.x > 0) {
        gemm1_body(blockIdx.x - 1, x, W1, as_w, ad_w,
                   sW, sW + IN_CH * D1, sW + IN_CH * D1 + H1 * C1);
        return;
    }
    // ---- block 0: single-block exclusive scan; seeds self-loops into CSR ----
    __shared__ int warp_sums[32];
    __shared__ int carry_s;
    int t = threadIdx.x;
    int lane = t & 31, warp = t >> 5;
    if (t == 0) carry_s = 0;
    __syncthreads();
    const int CHUNK = 4096;
    for (int base = 0; base < NN; base += CHUNK) {
        int idx = base + t * 4;
        int4 v4 = make_int4(0, 0, 0, 0);
        if (idx < NN) {
            v4 = *(const int4*)(g_deg + idx);
            *(int4*)(g_deg + idx) = make_int4(0, 0, 0, 0);
            v4.x += 1; v4.y += 1; v4.z += 1; v4.w += 1;   // self loops
        }
        int v = v4.x + v4.y + v4.z + v4.w;
        int incl = v;
        #pragma unroll
        for (int off = 1; off < 32; off <<= 1) {
            int nb = __shfl_up_sync(0xffffffffu, incl, off);
            if (lane >= off) incl += nb;
        }
        if (lane == 31) warp_sums[warp] = incl;
        __syncthreads();
        if (warp == 0) {
            int ws = warp_sums[lane];
            int wincl = ws;
            #pragma unroll
            for (int off = 1; off < 32; off <<= 1) {
                int nb = __shfl_up_sync(0xffffffffu, wincl, off);
                if (lane >= off) wincl += nb;
            }
            warp_sums[lane] = wincl - ws;
        }
        __syncthreads();
        int carry = carry_s;
        int excl = carry + warp_sums[warp] + incl - v;
        if (idx < NN) {
            int4 r;
            r.x = excl;
            r.y = r.x + v4.x;
            r.z = r.y + v4.y;
            r.w = r.z + v4.z;
            *(int4*)(g_rowptr + idx) = r;
            // seed self loop at row head; cursor starts one past it
            g_csrsrc[r.x] = idx;
            g_csrsrc[r.y] = idx + 1;
            g_csrsrc[r.z] = idx + 2;
            g_csrsrc[r.w] = idx + 3;
            int4 c;
            c.x = r.x + 1; c.y = r.y + 1; c.z = r.z + 1; c.w = r.w + 1;
            *(int4*)(g_cursor + idx) = c;
        }
        __syncthreads();
        if (t == 1023) carry_s = carry + warp_sums[31] + incl;
        __syncthreads();
    }
    if (t == 0) g_rowptr[NN] = carry_s;
}

// ---------------- scatter (pure, 4 edges/thread) ----------------
__global__ void __launch_bounds__(256) k_scatter(const int* __restrict__ ei) {
    int e4 = blockIdx.x * 256 + threadIdx.x;
    int e = e4 * 4;
    if (e + 4 <= EE) {
        int4 s = *(const int4*)(ei + e);
        int4 d = *(const int4*)(ei + EE + e);
        int s0 = atomicAdd(&g_cursor[d.x], 1);
        int s1 = atomicAdd(&g_cursor[d.y], 1);
        int s2 = atomicAdd(&g_cursor[d.z], 1);
        int s3 = atomicAdd(&g_cursor[d.w], 1);
        g_csrsrc[s0] = s.x;
        g_csrsrc[s1] = s.y;
        g_csrsrc[s2] = s.z;
        g_csrsrc[s3] = s.w;
    } else {
        for (; e < EE; e++) {
            int src = ei[e], dst = ei[EE + e];
            int slot = atomicAdd(&g_cursor[dst], 1);
            g_csrsrc[slot] = src;
        }
    }
}

__device__ __forceinline__ float lrelu(float e) { return e > 0.f ? e : NEG * e; }
__device__ __forceinline__ float elu(float v)   { return v > 0.f ? v : (__expf(v) - 1.f); }

__device__ __forceinline__ float sel4(float4 a, int q) {
    float w = a.x;
    w = (q == 1) ? a.y : w;
    w = (q == 2) ? a.z : w;
    w = (q == 3) ? a.w : w;
    return w;
}

// ---------------- GAT layer 1: R10 form (frozen) ----------------
__global__ void __launch_bounds__(128) k_edge1(const float* __restrict__ b1) {
    __shared__ int2 s_pk[4][32][4];
    int w = threadIdx.x >> 5;
    int lane = threadIdx.x & 31;
    int n = blockIdx.x * 4 + w;
    if (n >= NN) return;
    int beg = g_rowptr[n], end = g_rowptr[n + 1];
    float4 ad = *(const float4*)(g_ad1 + n * 4);
    const __half* hbase = g_h1h;

    int grp = lane >> 4;
    int sub = lane & 15;
    int q2  = sub >> 2;
    int choff = sub * 8;

    float s0 = 0.f, s1 = 0.f, s2 = 0.f, s3 = 0.f;
    float a[8];
    #pragma unroll
    for (int k = 0; k < 8; k++) a[k] = 0.f;

    for (int base = beg; base < end; base += 32) {
        int i = base + lane;
        int cnt = min(32, end - base);
        if (i < end) {
            int s = g_csrsrc[i];
            float4 as = *(const float4*)(g_as1 + s * 4);
            float e0 = __expf(lrelu(as.x + ad.x));
            float e1 = __expf(lrelu(as.y + ad.y));
            float e2 = __expf(lrelu(as.z + ad.z));
            float e3 = __expf(lrelu(as.w + ad.w));
            s0 += e0; s1 += e1; s2 += e2; s3 += e3;
            s_pk[w][lane][0] = make_int2(s, __float_as_int(e0));
            s_pk[w][lane][1] = make_int2(s, __float_as_int(e1));
            s_pk[w][lane][2] = make_int2(s, __float_as_int(e2));
            s_pk[w][lane][3] = make_int2(s, __float_as_int(e3));
        }
        __syncwarp();
        int j = 0;
        for (; j + 4 <= cnt; j += 4) {
            int2 pkA = s_pk[w][j + grp][q2];
            int2 pkB = s_pk[w][j + 2 + grp][q2];
            uint4 pA = *(const uint4*)(hbase + (size_t)pkA.x * D1 + choff);
            uint4 pB = *(const uint4*)(hbase + (size_t)pkB.x * D1 + choff);
            float wA = __int_as_float(pkA.y);
            float wB = __int_as_float(pkB.y);
            float2 f;
            f = __half22float2(*(__half2*)&pA.x); a[0] += wA * f.x; a[1] += wA * f.y;
            f = __half22float2(*(__half2*)&pA.y); a[2] += wA * f.x; a[3] += wA * f.y;
            f = __half22float2(*(__half2*)&pA.z); a[4] += wA * f.x; a[5] += wA * f.y;
            f = __half22float2(*(__half2*)&pA.w); a[6] += wA * f.x; a[7] += wA * f.y;
            f = __half22float2(*(__half2*)&pB.x); a[0] += wB * f.x; a[1] += wB * f.y;
            f = __half22float2(*(__half2*)&pB.y); a[2] += wB * f.x; a[3] += wB * f.y;
            f = __half22float2(*(__half2*)&pB.z); a[4] += wB * f.x; a[5] += wB * f.y;
            f = __half22float2(*(__half2*)&pB.w); a[6] += wB * f.x; a[7] += wB * f.y;
        }
        for (; j + 2 <= cnt; j += 2) {
            int2 pk = s_pk[w][j + grp][q2];
            uint4 p = *(const uint4*)(hbase + (size_t)pk.x * D1 + choff);
            float wj = __int_as_float(pk.y);
            float2 f;
            f = __half22float2(*(__half2*)&p.x); a[0] += wj * f.x; a[1] += wj * f.y;
            f = __half22float2(*(__half2*)&p.y); a[2] += wj * f.x; a[3] += wj * f.y;
            f = __half22float2(*(__half2*)&p.z); a[4] += wj * f.x; a[5] += wj * f.y;
            f = __half22float2(*(__half2*)&p.w); a[6] += wj * f.x; a[7] += wj * f.y;
        }
        if (j < cnt && grp == 0) {
            int2 pk = s_pk[w][j][q2];
            uint4 p = *(const uint4*)(hbase + (size_t)pk.x * D1 + choff);
            float wj = __int_as_float(pk.y);
            float2 f;
            f = __half22float2(*(__half2*)&p.x); a[0] += wj * f.x; a[1] += wj * f.y;
            f = __half22float2(*(__half2*)&p.y); a[2] += wj * f.x; a[3] += wj * f.y;
            f = __half22float2(*(__half2*)&p.z); a[4] += wj * f.x; a[5] += wj * f.y;
            f = __half22float2(*(__half2*)&p.w); a[6] += wj * f.x; a[7] += wj * f.y;
        }
        __syncwarp();
    }
    #pragma unroll
    for (int k = 0; k < 8; k++) a[k] += __shfl_xor_sync(0xffffffffu, a[k], 16);
    #pragma unroll
    for (int off = 16; off; off >>= 1) {
        s0 += __shfl_xor_sync(0xffffffffu, s0, off);
        s1 += __shfl_xor_sync(0xffffffffu, s1, off);
        s2 += __shfl_xor_sync(0xffffffffu, s2, off);
        s3 += __shfl_xor_sync(0xffffffffu, s3, off);
    }
    if (grp == 0) {
        float inv = sel4(make_float4(1.f/(s0+1e-16f), 1.f/(s1+1e-16f),
                                     1.f/(s2+1e-16f), 1.f/(s3+1e-16f)), q2);
        const float* bp = b1 + choff;
        uint4 pko;
        unsigned* pu = (unsigned*)&pko;
        #pragma unroll
        for (int k = 0; k < 4; k++) {
            float v0 = elu(a[2*k]   * inv + bp[2*k]);
            float v1 = elu(a[2*k+1] * inv + bp[2*k+1]);
            __half2 hh = __floats2half2_rn(v0, v1);
            pu[k] = *(unsigned*)&hh;
        }
        *(uint4*)(g_out1h + (size_t)n * D1 + choff) = pko;
    }
}

// ---------------- GEMM2 + attention logits (frozen) ----------------
__global__ void k_gemm2(const float* __restrict__ W2,
                        const float* __restrict__ as_w,
                        const float* __restrict__ ad_w) {
    __shared__ float sW[D1 * C2];
    __shared__ float sAs[C2], sAd[C2];
    int t = threadIdx.x;
    for (int i = t; i < D1 * C2; i += 256) sW[i] = W2[i];
    if (t < C2) { sAs[t] = as_w[t]; sAd[t] = ad_w[t]; }
    __syncthreads();
    int n = blockIdx.x * blockDim.x + t;
    if (n >= NN) return;

    float acc[C2];
    #pragma unroll
    for (int c = 0; c < C2; c++) acc[c] = 0.f;
    const uint4* xp = (const uint4*)(g_out1h + (size_t)n * D1);
    #pragma unroll 2
    for (int k8 = 0; k8 < 16; k8++) {
        uint4 u = xp[k8];
        float2 f0 = __half22float2(*(__half2*)&u.x);
        float2 f1 = __half22float2(*(__half2*)&u.y);
        float2 f2 = __half22float2(*(__half2*)&u.z);
        float2 f3 = __half22float2(*(__half2*)&u.w);
        const float* w0 = sW + (k8 * 8) * C2;
        #pragma unroll
        for (int c = 0; c < C2; c++) {
            acc[c] += f0.x * w0[c]        + f0.y * w0[C2 + c]
                    + f1.x * w0[2*C2 + c] + f1.y * w0[3*C2 + c]
                    + f2.x * w0[4*C2 + c] + f2.y * w0[5*C2 + c]
                    + f3.x * w0[6*C2 + c] + f3.y * w0[7*C2 + c];
        }
    }
    float asum = 0.f, dsum = 0.f;
    #pragma unroll
    for (int c = 0; c < C2; c++) { asum += acc[c] * sAs[c]; dsum += acc[c] * sAd[c]; }
    g_as2[n] = asum;
    g_ad2[n] = dsum;
    uint4 pk[2];
    unsigned* pu = (unsigned*)pk;
    #pragma unroll
    for (int i = 0; i < 8; i++) {
        __half2 hh = __floats2half2_rn(acc[2*i], acc[2*i+1]);
        pu[i] = *(unsigned*)&hh;
    }
    uint4* hp = (uint4*)(g_h2h + (size_t)n * C2);
    hp[0] = pk[0]; hp[1] = pk[1];
    uint4 pk2[2];
    unsigned* pu2 = (unsigned*)pk2;
    #pragma unroll
    for (int i = 0; i < 8; i++) {
        __half2 hh = __floats2half2_rn(acc[16 + 2*i], acc[16 + 2*i + 1]);
        pu2[i] = *(unsigned*)&hh;
    }
    hp[2] = pk2[0]; hp[3] = pk2[1];
}

// ---------------- GAT layer 2 + pooling (frozen R10 form) ----------------
__global__ void __launch_bounds__(128) k_edge2(const float* __restrict__ b2,
                        const int* __restrict__ batch) {
    __shared__ int2 s_pk[4][32];
    int w = threadIdx.x >> 5;
    int lane = threadIdx.x & 31;
    int n = blockIdx.x * 4 + w;
    if (n >= NN) return;
    int beg = g_rowptr[n], end = g_rowptr[n + 1];
    float ad = g_ad2[n];
    const __half* hbase = g_h2h;

    int grp = lane >> 4;
    int sub = lane & 15;
    int choff = sub * 2;

    float ssum = 0.f;
    float a0 = 0.f, a1 = 0.f;
    for (int base = beg; base < end; base += 32) {
        int i = base + lane;
        int cnt = min(32, end - base);
        if (i < end) {
            int s = g_csrsrc[i];
            float e = __expf(lrelu(g_as2[s] + ad));
            ssum += e;
            s_pk[w][lane] = make_int2(s, __float_as_int(e));
        }
        __syncwarp();
        int j = 0;
        for (; j + 4 <= cnt; j += 4) {
            int2 pkA = s_pk[w][j + grp];
            int2 pkB = s_pk[w][j + 2 + grp];
            unsigned uA = *(const unsigned*)(hbase + (size_t)pkA.x * C2 + choff);
            unsigned uB = *(const unsigned*)(hbase + (size_t)pkB.x * C2 + choff);
            float wA = __int_as_float(pkA.y);
            float wB = __int_as_float(pkB.y);
            float2 fA = __half22float2(*(__half2*)&uA);
            float2 fB = __half22float2(*(__half2*)&uB);
            a0 += wA * fA.x + wB * fB.x;
            a1 += wA * fA.y + wB * fB.y;
        }
        for (; j + 2 <= cnt; j += 2) {
            int2 pk = s_pk[w][j + grp];
            unsigned u = *(const unsigned*)(hbase + (size_t)pk.x * C2 + choff);
            float wj = __int_as_float(pk.y);
            float2 f = __half22float2(*(__half2*)&u);
            a0 += wj * f.x; a1 += wj * f.y;
        }
        if (j < cnt && grp == 0) {
            int2 pk = s_pk[w][j];
            unsigned u = *(const unsigned*)(hbase + (size_t)pk.x * C2 + choff);
            float wj = __int_as_float(pk.y);
            float2 f = __half22float2(*(__half2*)&u);
            a0 += wj * f.x; a1 += wj * f.y;
        }
        __syncwarp();
    }
    a0 += __shfl_xor_sync(0xffffffffu, a0, 16);
    a1 += __shfl_xor_sync(0xffffffffu, a1, 16);
    #pragma unroll
    for (int off = 16; off; off >>= 1) ssum += __shfl_xor_sync(0xffffffffu, ssum, off);
    float inv = 1.f / (ssum + 1e-16f);
    int gid = batch[n];
    if (grp == 0) {
        float v0 = elu(a0 * inv + b2[choff]);
        float v1 = elu(a1 * inv + b2[choff + 1]);
        float* pp = g_pool + gid * C2 + choff;
        atomicAdd(pp,     v0);
        atomicAdd(pp + 1, v1);
        if (sub == 0) atomicAdd(&g_cnt[gid], 1.0f);
    }
}

// ---------------- MLP head ----------------
__global__ void k_head(const float* __restrict__ Wh1, const float* __restrict__ bh1,
                       const float* __restrict__ Wh2, const float* __restrict__ bh2,
                       float* __restrict__ out) {
    int g = blockIdx.x * blockDim.x + threadIdx.x;
    if (g >= GG) return;
    float cnt = fmaxf(g_cnt[g], 1.0f);
    float invc = 1.f / cnt;
    float p[C2];
    #pragma unroll
    for (int c = 0; c < C2; c++) p[c] = g_pool[g * C2 + c] * invc;
    float o = bh2[0];
    for (int j = 0; j < 64; j++) {
        float a = bh1[j];
        #pragma unroll
        for (int c = 0; c < C2; c++) a += p[c] * Wh1[c * 64 + j];
        a = fmaxf(a, 0.f);
        o += a * Wh2[j];
    }
    out[g] = o;
}

// ---------------- launch ----------------
extern "C" void kernel_launch(void* const* d_in, const int* in_sizes, int n_in,
                              void* d_out, int out_size) {
    const float* x     = (const float*)d_in[0];
    const int*   ei    = (const int*)d_in[1];
    const int*   batch = (const int*)d_in[2];
    const float* W1   = (const float*)d_in[3];
    const float* as1  = (const float*)d_in[4];
    const float* ad1  = (const float*)d_in[5];
    const float* b1   = (const float*)d_in[6];
    const float* W2   = (const float*)d_in[7];
    const float* as2  = (const float*)d_in[8];
    const float* ad2  = (const float*)d_in[9];
    const float* b2   = (const float*)d_in[10];
    const float* Wh1  = (const float*)d_in[11];
    const float* bh1  = (const float*)d_in[12];
    const float* Wh2  = (const float*)d_in[13];
    const float* bh2  = (const float*)d_in[14];
    float* out = (float*)d_out;

    k_degree<<<DEG_BLOCKS + 1, 256>>>(ei);
    k_scan_gemm1<<<1 + GEMM1_BLOCKS, 1024>>>(x, W1, as1, ad1);
    k_scatter<<<SCAT_BLOCKS, 256>>>(ei);
    k_edge1<<<(NN + 3) / 4, 128>>>(b1);
    k_gemm2<<<(NN + 255) / 256, 256>>>(W2, as2, ad2);
    k_edge2<<<(NN + 3) / 4, 128>>>(b2, batch);
    k_head<<<1, 128>>>(Wh1, bh1, Wh2, bh2, out);
}

// round 17
// speedup vs baseline: 1.1261x; 1.1261x over previous
#include <cuda_runtime.h>
#include <cuda_fp16.h>
#include <math.h>

#define NN 50000
#define EE 1600000
#define ET (EE + NN)
#define GG 100
#define IN_CH 16
#define H1 4
#define C1 32
#define D1 (H1*C1)
#define C2 32
#define NEG 0.2f

#define DEG_BLOCKS ((EE / 4 + 255) / 256)
#define SCAT_THREADS (EE / 2 + NN)
#define SCAT_BLOCKS ((SCAT_THREADS + 255) / 256)
#define GEMM1_BLOCKS ((NN + 255) / 256)   // 1024-thread blocks: 256 nodes each

// ---------------- scratch ----------------
__device__ __align__(16) int g_deg[NN + 4];
__device__ __align__(16) int g_rowptr[NN + 4];
__device__ __align__(16) int g_cursor[NN + 4];
__device__ __align__(16) int g_csrsrc[ET + 4];
__device__ __align__(16) __half g_h1h[NN * D1];
__device__ __align__(16) float  g_as1[NN * H1];
__device__ __align__(16) float  g_ad1[NN * H1];
__device__ __align__(16) __half g_out1h[NN * D1];
__device__ __align__(16) __half g_h2h[NN * C2];
__device__ float g_as2[NN];
__device__ float g_ad2[NN];
__device__ float g_pool[GG * C2];
__device__ float g_cnt[GG];

// ---------------- degree (int4, 4 edges/thread) + pool init ----------------
__global__ void k_degree(const int* __restrict__ ei) {
    int b = blockIdx.x;
    if (b < DEG_BLOCKS) {
        int e4 = b * 256 + threadIdx.x;
        if (e4 * 4 < EE) {
            int4 d = *(const int4*)(ei + EE + e4 * 4);
            atomicAdd(&g_deg[d.x], 1);
            atomicAdd(&g_deg[d.y], 1);
            atomicAdd(&g_deg[d.z], 1);
            atomicAdd(&g_deg[d.w], 1);
        }
    } else {
        int i = threadIdx.x;
        for (; i < GG * C2; i += 256) g_pool[i] = 0.f;
        int j = threadIdx.x;
        if (j < GG) g_cnt[j] = 0.f;
    }
}

// ---------------- GEMM1 body (flexible block size) ----------------
__device__ __forceinline__ void gemm1_body(int blk,
                        const float* __restrict__ x,
                        const float* __restrict__ W1,
                        const float* __restrict__ as_w,
                        const float* __restrict__ ad_w,
                        float* sW, float* sAs, float* sAd) {
    int t = threadIdx.x;
    int nthr = blockDim.x;
    for (int i = t; i < IN_CH * D1; i += nthr) sW[i] = W1[i];
    if (t < H1 * C1) { sAs[t] = as_w[t]; sAd[t] = ad_w[t]; }
    __syncthreads();

    int warp = t >> 5, lane = t & 31;
    int h = warp & 3;
    int nodes_per_blk = (nthr >> 2);
    int n = blk * nodes_per_blk + (warp >> 2) * 32 + lane;
    if (n >= NN) return;

    float xv[16];
    const float4* xp = (const float4*)(x + (size_t)n * IN_CH);
    #pragma unroll
    for (int i = 0; i < 4; i++) {
        float4 r = xp[i];
        xv[4*i]=r.x; xv[4*i+1]=r.y; xv[4*i+2]=r.z; xv[4*i+3]=r.w;
    }
    float acc[C1];
    #pragma unroll
    for (int c = 0; c < C1; c++) acc[c] = 0.f;
    #pragma unroll
    for (int k = 0; k < IN_CH; k++) {
        float xk = xv[k];
        const float* wrow = sW + k * D1 + h * C1;
        #pragma unroll
        for (int c = 0; c < C1; c++) acc[c] += xk * wrow[c];
    }
    float asum = 0.f, dsum = 0.f;
    #pragma unroll
    for (int c = 0; c < C1; c++) { asum += acc[c] * sAs[h*C1+c]; dsum += acc[c] * sAd[h*C1+c]; }
    g_as1[n * H1 + h] = asum;
    g_ad1[n * H1 + h] = dsum;
    uint4 pk[4];
    unsigned* pu = (unsigned*)pk;
    #pragma unroll
    for (int i = 0; i < 16; i++) {
        __half2 hh = __floats2half2_rn(acc[2*i], acc[2*i+1]);
        pu[i] = *(unsigned*)&hh;
    }
    uint4* hp = (uint4*)(g_h1h + (size_t)n * D1 + h * C1);
    #pragma unroll
    for (int i = 0; i < 4; i++) hp[i] = pk[i];
}

// ---------------- fat kernel: scan (block 0) + gemm1 (blocks 1..) — R15 form ----------------
__global__ void __launch_bounds__(1024) k_scan_gemm1(
        const float* __restrict__ x,
        const float* __restrict__ W1,
        const float* __restrict__ as_w,
        const float* __restrict__ ad_w) {
    __shared__ float sW[IN_CH * D1 + 2 * H1 * C1];
    if (blockIdx.x > 0) {
        gemm1_body(blockIdx.x - 1, x, W1, as_w, ad_w,
                   sW, sW + IN_CH * D1, sW + IN_CH * D1 + H1 * C1);
        return;
    }
    __shared__ int warp_sums[32];
    __shared__ int carry_s;
    int t = threadIdx.x;
    int lane = t & 31, warp = t >> 5;
    if (t == 0) carry_s = 0;
    __syncthreads();
    const int CHUNK = 4096;
    for (int base = 0; base < NN; base += CHUNK) {
        int idx = base + t * 4;
        int4 v4 = make_int4(0, 0, 0, 0);
        if (idx < NN) {
            v4 = *(const int4*)(g_deg + idx);
            *(int4*)(g_deg + idx) = make_int4(0, 0, 0, 0);
            v4.x += 1; v4.y += 1; v4.z += 1; v4.w += 1;   // self loops
        }
        int v = v4.x + v4.y + v4.z + v4.w;
        int incl = v;
        #pragma unroll
        for (int off = 1; off < 32; off <<= 1) {
            int nb = __shfl_up_sync(0xffffffffu, incl, off);
            if (lane >= off) incl += nb;
        }
        if (lane == 31) warp_sums[warp] = incl;
        __syncthreads();
        if (warp == 0) {
            int ws = warp_sums[lane];
            int wincl = ws;
            #pragma unroll
            for (int off = 1; off < 32; off <<= 1) {
                int nb = __shfl_up_sync(0xffffffffu, wincl, off);
                if (lane >= off) wincl += nb;
            }
            warp_sums[lane] = wincl - ws;
        }
        __syncthreads();
        int carry = carry_s;
        int excl = carry + warp_sums[warp] + incl - v;
        if (idx < NN) {
            int4 r;
            r.x = excl;
            r.y = r.x + v4.x;
            r.z = r.y + v4.y;
            r.w = r.z + v4.z;
            *(int4*)(g_rowptr + idx) = r;
            *(int4*)(g_cursor + idx) = r;
        }
        __syncthreads();
        if (t == 1023) carry_s = carry + warp_sums[31] + incl;
        __syncthreads();
    }
    if (t == 0) g_rowptr[NN] = carry_s;
}

// ---------------- scatter: 2 edges/thread (int2) + self-loop tail threads ----------------
__global__ void __launch_bounds__(256) k_scatter(const int* __restrict__ ei) {
    int t = blockIdx.x * 256 + threadIdx.x;
    if (t < EE / 2) {
        int e = t * 2;
        int2 s = *(const int2*)(ei + e);
        int2 d = *(const int2*)(ei + EE + e);
        int s0 = atomicAdd(&g_cursor[d.x], 1);
        int s1 = atomicAdd(&g_cursor[d.y], 1);
        g_csrsrc[s0] = s.x;
        g_csrsrc[s1] = s.y;
    } else if (t < SCAT_THREADS) {
        int n = t - EE / 2;         // self loop for node n
        int slot = atomicAdd(&g_cursor[n], 1);
        g_csrsrc[slot] = n;
    }
}

__device__ __forceinline__ float lrelu(float e) { return e > 0.f ? e : NEG * e; }
__device__ __forceinline__ float elu(float v)   { return v > 0.f ? v : (__expf(v) - 1.f); }

__device__ __forceinline__ float sel4(float4 a, int q) {
    float w = a.x;
    w = (q == 1) ? a.y : w;
    w = (q == 2) ? a.z : w;
    w = (q == 3) ? a.w : w;
    return w;
}

// ---------------- GAT layer 1: R10 form (frozen) ----------------
__global__ void __launch_bounds__(128) k_edge1(const float* __restrict__ b1) {
    __shared__ int2 s_pk[4][32][4];
    int w = threadIdx.x >> 5;
    int lane = threadIdx.x & 31;
    int n = blockIdx.x * 4 + w;
    if (n >= NN) return;
    int beg = g_rowptr[n], end = g_rowptr[n + 1];
    float4 ad = *(const float4*)(g_ad1 + n * 4);
    const __half* hbase = g_h1h;

    int grp = lane >> 4;
    int sub = lane & 15;
    int q2  = sub >> 2;
    int choff = sub * 8;

    float s0 = 0.f, s1 = 0.f, s2 = 0.f, s3 = 0.f;
    float a[8];
    #pragma unroll
    for (int k = 0; k < 8; k++) a[k] = 0.f;

    for (int base = beg; base < end; base += 32) {
        int i = base + lane;
        int cnt = min(32, end - base);
        if (i < end) {
            int s = g_csrsrc[i];
            float4 as = *(const float4*)(g_as1 + s * 4);
            float e0 = __expf(lrelu(as.x + ad.x));
            float e1 = __expf(lrelu(as.y + ad.y));
            float e2 = __expf(lrelu(as.z + ad.z));
            float e3 = __expf(lrelu(as.w + ad.w));
            s0 += e0; s1 += e1; s2 += e2; s3 += e3;
            s_pk[w][lane][0] = make_int2(s, __float_as_int(e0));
            s_pk[w][lane][1] = make_int2(s, __float_as_int(e1));
            s_pk[w][lane][2] = make_int2(s, __float_as_int(e2));
            s_pk[w][lane][3] = make_int2(s, __float_as_int(e3));
        }
        __syncwarp();
        int j = 0;
        for (; j + 4 <= cnt; j += 4) {
            int2 pkA = s_pk[w][j + grp][q2];
            int2 pkB = s_pk[w][j + 2 + grp][q2];
            uint4 pA = *(const uint4*)(hbase + (size_t)pkA.x * D1 + choff);
            uint4 pB = *(const uint4*)(hbase + (size_t)pkB.x * D1 + choff);
            float wA = __int_as_float(pkA.y);
            float wB = __int_as_float(pkB.y);
            float2 f;
            f = __half22float2(*(__half2*)&pA.x); a[0] += wA * f.x; a[1] += wA * f.y;
            f = __half22float2(*(__half2*)&pA.y); a[2] += wA * f.x; a[3] += wA * f.y;
            f = __half22float2(*(__half2*)&pA.z); a[4] += wA * f.x; a[5] += wA * f.y;
            f = __half22float2(*(__half2*)&pA.w); a[6] += wA * f.x; a[7] += wA * f.y;
            f = __half22float2(*(__half2*)&pB.x); a[0] += wB * f.x; a[1] += wB * f.y;
            f = __half22float2(*(__half2*)&pB.y); a[2] += wB * f.x; a[3] += wB * f.y;
            f = __half22float2(*(__half2*)&pB.z); a[4] += wB * f.x; a[5] += wB * f.y;
            f = __half22float2(*(__half2*)&pB.w); a[6] += wB * f.x; a[7] += wB * f.y;
        }
        for (; j + 2 <= cnt; j += 2) {
            int2 pk = s_pk[w][j + grp][q2];
            uint4 p = *(const uint4*)(hbase + (size_t)pk.x * D1 + choff);
            float wj = __int_as_float(pk.y);
            float2 f;
            f = __half22float2(*(__half2*)&p.x); a[0] += wj * f.x; a[1] += wj * f.y;
            f = __half22float2(*(__half2*)&p.y); a[2] += wj * f.x; a[3] += wj * f.y;
            f = __half22float2(*(__half2*)&p.z); a[4] += wj * f.x; a[5] += wj * f.y;
            f = __half22float2(*(__half2*)&p.w); a[6] += wj * f.x; a[7] += wj * f.y;
        }
        if (j < cnt && grp == 0) {
            int2 pk = s_pk[w][j][q2];
            uint4 p = *(const uint4*)(hbase + (size_t)pk.x * D1 + choff);
            float wj = __int_as_float(pk.y);
            float2 f;
            f = __half22float2(*(__half2*)&p.x); a[0] += wj * f.x; a[1] += wj * f.y;
            f = __half22float2(*(__half2*)&p.y); a[2] += wj * f.x; a[3] += wj * f.y;
            f = __half22float2(*(__half2*)&p.z); a[4] += wj * f.x; a[5] += wj * f.y;
            f = __half22float2(*(__half2*)&p.w); a[6] += wj * f.x; a[7] += wj * f.y;
        }
        __syncwarp();
    }
    #pragma unroll
    for (int k = 0; k < 8; k++) a[k] += __shfl_xor_sync(0xffffffffu, a[k], 16);
    #pragma unroll
    for (int off = 16; off; off >>= 1) {
        s0 += __shfl_xor_sync(0xffffffffu, s0, off);
        s1 += __shfl_xor_sync(0xffffffffu, s1, off);
        s2 += __shfl_xor_sync(0xffffffffu, s2, off);
        s3 += __shfl_xor_sync(0xffffffffu, s3, off);
    }
    if (grp == 0) {
        float inv = sel4(make_float4(1.f/(s0+1e-16f), 1.f/(s1+1e-16f),
                                     1.f/(s2+1e-16f), 1.f/(s3+1e-16f)), q2);
        const float* bp = b1 + choff;
        uint4 pko;
        unsigned* pu = (unsigned*)&pko;
        #pragma unroll
        for (int k = 0; k < 4; k++) {
            float v0 = elu(a[2*k]   * inv + bp[2*k]);
            float v1 = elu(a[2*k+1] * inv + bp[2*k+1]);
            __half2 hh = __floats2half2_rn(v0, v1);
            pu[k] = *(unsigned*)&hh;
        }
        *(uint4*)(g_out1h + (size_t)n * D1 + choff) = pko;
    }
}

// ---------------- GEMM2 + attention logits (frozen) ----------------
__global__ void k_gemm2(const float* __restrict__ W2,
                        const float* __restrict__ as_w,
                        const float* __restrict__ ad_w) {
    __shared__ float sW[D1 * C2];
    __shared__ float sAs[C2], sAd[C2];
    int t = threadIdx.x;
    for (int i = t; i < D1 * C2; i += 256) sW[i] = W2[i];
    if (t < C2) { sAs[t] = as_w[t]; sAd[t] = ad_w[t]; }
    __syncthreads();
    int n = blockIdx.x * blockDim.x + t;
    if (n >= NN) return;

    float acc[C2];
    #pragma unroll
    for (int c = 0; c < C2; c++) acc[c] = 0.f;
    const uint4* xp = (const uint4*)(g_out1h + (size_t)n * D1);
    #pragma unroll 2
    for (int k8 = 0; k8 < 16; k8++) {
        uint4 u = xp[k8];
        float2 f0 = __half22float2(*(__half2*)&u.x);
        float2 f1 = __half22float2(*(__half2*)&u.y);
        float2 f2 = __half22float2(*(__half2*)&u.z);
        float2 f3 = __half22float2(*(__half2*)&u.w);
        const float* w0 = sW + (k8 * 8) * C2;
        #pragma unroll
        for (int c = 0; c < C2; c++) {
            acc[c] += f0.x * w0[c]        + f0.y * w0[C2 + c]
                    + f1.x * w0[2*C2 + c] + f1.y * w0[3*C2 + c]
                    + f2.x * w0[4*C2 + c] + f2.y * w0[5*C2 + c]
                    + f3.x * w0[6*C2 + c] + f3.y * w0[7*C2 + c];
        }
    }
    float asum = 0.f, dsum = 0.f;
    #pragma unroll
    for (int c = 0; c < C2; c++) { asum += acc[c] * sAs[c]; dsum += acc[c] * sAd[c]; }
    g_as2[n] = asum;
    g_ad2[n] = dsum;
    uint4 pk[2];
    unsigned* pu = (unsigned*)pk;
    #pragma unroll
    for (int i = 0; i < 8; i++) {
        __half2 hh = __floats2half2_rn(acc[2*i], acc[2*i+1]);
        pu[i] = *(unsigned*)&hh;
    }
    uint4* hp = (uint4*)(g_h2h + (size_t)n * C2);
    hp[0] = pk[0]; hp[1] = pk[1];
    uint4 pk2[2];
    unsigned* pu2 = (unsigned*)pk2;
    #pragma unroll
    for (int i = 0; i < 8; i++) {
        __half2 hh = __floats2half2_rn(acc[16 + 2*i], acc[16 + 2*i + 1]);
        pu2[i] = *(unsigned*)&hh;
    }
    hp[2] = pk2[0]; hp[3] = pk2[1];
}

// ---------------- GAT layer 2 + pooling (frozen R10 form) ----------------
__global__ void __launch_bounds__(128) k_edge2(const float* __restrict__ b2,
                        const int* __restrict__ batch) {
    __shared__ int2 s_pk[4][32];
    int w = threadIdx.x >> 5;
    int lane = threadIdx.x & 31;
    int n = blockIdx.x * 4 + w;
    if (n >= NN) return;
    int beg = g_rowptr[n], end = g_rowptr[n + 1];
    float ad = g_ad2[n];
    const __half* hbase = g_h2h;

    int grp = lane >> 4;
    int sub = lane & 15;
    int choff = sub * 2;

    float ssum = 0.f;
    float a0 = 0.f, a1 = 0.f;
    for (int base = beg; base < end; base += 32) {
        int i = base + lane;
        int cnt = min(32, end - base);
        if (i < end) {
            int s = g_csrsrc[i];
            float e = __expf(lrelu(g_as2[s] + ad));
            ssum += e;
            s_pk[w][lane] = make_int2(s, __float_as_int(e));
        }
        __syncwarp();
        int j = 0;
        for (; j + 4 <= cnt; j += 4) {
            int2 pkA = s_pk[w][j + grp];
            int2 pkB = s_pk[w][j + 2 + grp];
            unsigned uA = *(const unsigned*)(hbase + (size_t)pkA.x * C2 + choff);
            unsigned uB = *(const unsigned*)(hbase + (size_t)pkB.x * C2 + choff);
            float wA = __int_as_float(pkA.y);
            float wB = __int_as_float(pkB.y);
            float2 fA = __half22float2(*(__half2*)&uA);
            float2 fB = __half22float2(*(__half2*)&uB);
            a0 += wA * fA.x + wB * fB.x;
            a1 += wA * fA.y + wB * fB.y;
        }
        for (; j + 2 <= cnt; j += 2) {
            int2 pk = s_pk[w][j + grp];
            unsigned u = *(const unsigned*)(hbase + (size_t)pk.x * C2 + choff);
            float wj = __int_as_float(pk.y);
            float2 f = __half22float2(*(__half2*)&u);
            a0 += wj * f.x; a1 += wj * f.y;
        }
        if (j < cnt && grp == 0) {
            int2 pk = s_pk[w][j];
            unsigned u = *(const unsigned*)(hbase + (size_t)pk.x * C2 + choff);
            float wj = __int_as_float(pk.y);
            float2 f = __half22float2(*(__half2*)&u);
            a0 += wj * f.x; a1 += wj * f.y;
        }
        __syncwarp();
    }
    a0 += __shfl_xor_sync(0xffffffffu, a0, 16);
    a1 += __shfl_xor_sync(0xffffffffu, a1, 16);
    #pragma unroll
    for (int off = 16; off; off >>= 1) ssum += __shfl_xor_sync(0xffffffffu, ssum, off);
    float inv = 1.f / (ssum + 1e-16f);
    int gid = batch[n];
    if (grp == 0) {
        float v0 = elu(a0 * inv + b2[choff]);
        float v1 = elu(a1 * inv + b2[choff + 1]);
        float* pp = g_pool + gid * C2 + choff;
        atomicAdd(pp,     v0);
        atomicAdd(pp + 1, v1);
        if (sub == 0) atomicAdd(&g_cnt[gid], 1.0f);
    }
}

// ---------------- MLP head ----------------
__global__ void k_head(const float* __restrict__ Wh1, const float* __restrict__ bh1,
                       const float* __restrict__ Wh2, const float* __restrict__ bh2,
                       float* __restrict__ out) {
    int g = blockIdx.x * blockDim.x + threadIdx.x;
    if (g >= GG) return;
    float cnt = fmaxf(g_cnt[g], 1.0f);
    float invc = 1.f / cnt;
    float p[C2];
    #pragma unroll
    for (int c = 0; c < C2; c++) p[c] = g_pool[g * C2 + c] * invc;
    float o = bh2[0];
    for (int j = 0; j < 64; j++) {
        float a = bh1[j];
        #pragma unroll
        for (int c = 0; c < C2; c++) a += p[c] * Wh1[c * 64 + j];
        a = fmaxf(a, 0.f);
        o += a * Wh2[j];
    }
    out[g] = o;
}

// ---------------- launch ----------------
extern "C" void kernel_launch(void* const* d_in, const int* in_sizes, int n_in,
                              void* d_out, int out_size) {
    const float* x     = (const float*)d_in[0];
    const int*   ei    = (const int*)d_in[1];
    const int*   batch = (const int*)d_in[2];
    const float* W1   = (const float*)d_in[3];
    const float* as1  = (const float*)d_in[4];
    const float* ad1  = (const float*)d_in[5];
    const float* b1   = (const float*)d_in[6];
    const float* W2   = (const float*)d_in[7];
    const float* as2  = (const float*)d_in[8];
    const float* ad2  = (const float*)d_in[9];
    const float* b2   = (const float*)d_in[10];
    const float* Wh1  = (const float*)d_in[11];
    const float* bh1  = (const float*)d_in[12];
    const float* Wh2  = (const float*)d_in[13];
    const float* bh2  = (const float*)d_in[14];
    float* out = (float*)d_out;

    k_degree<<<DEG_BLOCKS + 1, 256>>>(ei);
    k_scan_gemm1<<<1 + GEMM1_BLOCKS, 1024>>>(x, W1, as1, ad1);
    k_scatter<<<SCAT_BLOCKS, 256>>>(ei);
    k_edge1<<<(NN + 3) / 4, 128>>>(b1);
    k_gemm2<<<(NN + 255) / 256, 256>>>(W2, as2, ad2);
    k_edge2<<<(NN + 3) / 4, 128>>>(b2, batch);
    k_head<<<1, 128>>>(Wh1, bh1, Wh2, bh2, out);
}